// round 12
// baseline (speedup 1.0000x reference)
#include <cuda_runtime.h>
#include <cstdint>

#define D       128
#define NROWS   20000
#define NPAD    20480
#define NA      1024
#define TA      16        // anchors per CTA (fused CTA-pair: 1024 threads)
#define CROWS   1024
#define NCHUNK  20
#define KSEL    8
#define KTOP    10
#define GAMMA   1.0f
#define SCALE   25.4f     // int8 quant scale, selection-only
#define QB      79        // quant row-blocks (79*256 >= 20000)

typedef unsigned int uint;

// Static device scratch (allocation-free rule: __device__ globals only)
__device__ __align__(16) uint g_qT[2][D / 4][NPAD];     // transposed packed DB
__device__ __align__(16) uint g_anchq[2][NA][D / 4];    // packed quantized anchors
__device__ __align__(16) float g_anch[2][NA][D];        // fp32 anchors
__device__ float g_Dm[NA];                              // positive dist + gamma
__device__ int   g_candi[2][NA][NCHUNK * KSEL];         // candidate row indices
__device__ float g_partial[2 * NA];                     // per-anchor loss

// Fused SAD-accumulate: acc += sum_bytes(|s8(a) - s8(b)|)  (single SASS op)
__device__ __forceinline__ void sad4(uint& acc, uint a, uint b) {
    asm("vabsdiff4.u32.s32.s32.add %0, %1, %2, %0;" : "+r"(acc) : "r"(a), "r"(b));
}

__device__ __forceinline__ uint quant_pack4(float4 f) {
    int x = __float2int_rn(fminf(fmaxf(f.x * SCALE, -127.f), 127.f));
    int y = __float2int_rn(fminf(fmaxf(f.y * SCALE, -127.f), 127.f));
    int z = __float2int_rn(fminf(fmaxf(f.z * SCALE, -127.f), 127.f));
    int w = __float2int_rn(fminf(fmaxf(f.w * SCALE, -127.f), 127.f));
    return (uint)(x & 255) | ((uint)(y & 255) << 8) |
           ((uint)(z & 255) << 16) | ((uint)(w & 255) << 24);
}

// ---------------------------------------------------------------------------
// Prep: quantize+transpose DBs (blocks 0..2*QB-1) and gather anchors.
// ---------------------------------------------------------------------------
__global__ void k_prep(const float* __restrict__ out1,
                       const float* __restrict__ out2,
                       const int* __restrict__ an1,
                       const int* __restrict__ an2) {
    int b = blockIdx.x;
    int tid = threadIdx.x;
    if (b < 2 * QB) {
        int side = (b >= QB);
        const float* src = side ? out1 : out2;
        int row = (side ? b - QB : b) * 256 + tid;
        if (row >= NROWS) return;
        const float4* s = (const float4*)(src + (size_t)row * D);
        #pragma unroll
        for (int j = 0; j < D / 4; j++)
            g_qT[side][j][row] = quant_pack4(s[j]);
        return;
    }
    // gather: 2 anchors per block, 128 threads each
    int i = (b - 2 * QB) * 2 + (tid >> 7);
    int d = tid & 127;
    float v1 = out1[(size_t)an1[i] * D + d];
    float v2 = out2[(size_t)an2[i] * D + d];
    g_anch[0][i][d] = v1;
    g_anch[1][i][d] = v2;
    int q1 = __float2int_rn(fminf(fmaxf(v1 * SCALE, -127.f), 127.f)) & 255;
    int q2 = __float2int_rn(fminf(fmaxf(v2 * SCALE, -127.f), 127.f)) & 255;
    __shared__ unsigned char b1[2][D], b2[2][D];
    int h = tid >> 7;
    b1[h][d] = (unsigned char)q1;
    b2[h][d] = (unsigned char)q2;
    __syncthreads();
    if (d < D / 4) {
        g_anchq[0][i][d] = ((const uint*)b1[h])[d];
        g_anchq[1][i][d] = ((const uint*)b2[h])[d];
    }
    float x = fabsf(v1 - v2);
    #pragma unroll
    for (int off = 16; off; off >>= 1) x += __shfl_down_sync(0xffffffffu, x, off);
    __shared__ float ws[8];
    if ((tid & 31) == 0) ws[tid >> 5] = x;
    __syncthreads();
    if (d == 0) g_Dm[i] = ws[4 * h] + ws[4 * h + 1] + ws[4 * h + 2] + ws[4 * h + 3] + GAMMA;
}

// ---------------------------------------------------------------------------
// int8 SAD distances + per-chunk top-8 selection.
// Grid (64 tiles, 20 chunks, 2 sides), 1024 threads, 1 CTA/SM.
// All 32 warps share ONE 128KB chunk slice -> fits L1D (228-67KB smem).
// Thread = 4 anchors (its quarter) x 4 rows {2p,2p+1,2p+512,2p+513}.
// Inner loop byte-identical to the proven round-6/11 mainloop.
// ---------------------------------------------------------------------------
#define SM_AQ_BYTES   (TA * (D / 4) * 4)        // 2048
#define SM_DIST_BYTES (TA * CROWS * 4)          // 65536
#define SM_CAND_BYTES (TA * 2 * KSEL * 4)       // 1024
#define SM_TOTAL (SM_AQ_BYTES + SM_DIST_BYTES + SM_CAND_BYTES)

__global__ void __launch_bounds__(1024, 1) k_dist() {
    extern __shared__ __align__(16) char dynsmem[];
    uint* sh_aq  = (uint*)dynsmem;                          // [16][32]
    int* sh_dist = (int*)(dynsmem + SM_AQ_BYTES);           // [16][1024]
    int* sh_cand = (int*)(dynsmem + SM_AQ_BYTES + SM_DIST_BYTES); // [16][2][8]

    int tile  = blockIdx.x;
    int chunk = blockIdx.y;
    int side  = blockIdx.z;
    int tid = threadIdx.x;
    int grp = tid >> 8;           // anchor quarter: 0..3 -> anchors 4*grp..
    int pos = tid & 255;

    if (tid < TA * (D / 4))
        sh_aq[tid] = g_anchq[side][tile * TA + (tid >> 5)][tid & 31];
    __syncthreads();

    uint acc[4][4];
    #pragma unroll
    for (int t = 0; t < 4; t++)
        #pragma unroll
        for (int r = 0; r < 4; r++) acc[t][r] = 0;

    const int p2 = 2 * pos;       // local rows p2, p2+1, p2+512, p2+513
    const uint* __restrict__ qp = &g_qT[side][0][0] + chunk * CROWS + p2;
    const int ta0 = grp * 4;

    #pragma unroll
    for (int jb = 0; jb < 8; jb++) {
        uint4 a0 = *(const uint4*)&sh_aq[(ta0 + 0) * 32 + 4 * jb];
        uint4 a1 = *(const uint4*)&sh_aq[(ta0 + 1) * 32 + 4 * jb];
        uint4 a2 = *(const uint4*)&sh_aq[(ta0 + 2) * 32 + 4 * jb];
        uint4 a3 = *(const uint4*)&sh_aq[(ta0 + 3) * 32 + 4 * jb];
        #pragma unroll
        for (int jj = 0; jj < 4; jj++) {
            int j = 4 * jb + jj;
            uint2 bA = *(const uint2*)(qp + (size_t)j * NPAD);        // rows p2,p2+1
            uint2 bB = *(const uint2*)(qp + (size_t)j * NPAD + 512);  // +512,+513
            uint av0 = jj == 0 ? a0.x : jj == 1 ? a0.y : jj == 2 ? a0.z : a0.w;
            uint av1 = jj == 0 ? a1.x : jj == 1 ? a1.y : jj == 2 ? a1.z : a1.w;
            uint av2 = jj == 0 ? a2.x : jj == 1 ? a2.y : jj == 2 ? a2.z : a2.w;
            uint av3 = jj == 0 ? a3.x : jj == 1 ? a3.y : jj == 2 ? a3.z : a3.w;
            sad4(acc[0][0], av0, bA.x);
            sad4(acc[0][1], av0, bA.y);
            sad4(acc[0][2], av0, bB.x);
            sad4(acc[0][3], av0, bB.y);
            sad4(acc[1][0], av1, bA.x);
            sad4(acc[1][1], av1, bA.y);
            sad4(acc[1][2], av1, bB.x);
            sad4(acc[1][3], av1, bB.y);
            sad4(acc[2][0], av2, bA.x);
            sad4(acc[2][1], av2, bA.y);
            sad4(acc[2][2], av2, bB.x);
            sad4(acc[2][3], av2, bB.y);
            sad4(acc[3][0], av3, bA.x);
            sad4(acc[3][1], av3, bA.y);
            sad4(acc[3][2], av3, bB.x);
            sad4(acc[3][3], av3, bB.y);
        }
    }

    // Store packed (sad<<10 | idx); invalid rows -> INT_MAX.
    const int nb = chunk * CROWS;
    #pragma unroll
    for (int r = 0; r < 4; r++) {
        int idx = (r & 1) + ((r >> 1) << 9) + p2;   // p2, p2+1, p2+512, p2+513
        bool valid = (nb + idx) < NROWS;
        #pragma unroll
        for (int t = 0; t < 4; t++) {
            int v = valid ? (int)((acc[t][r] << 10) | (uint)idx) : 0x7fffffff;
            sh_dist[(ta0 + t) * CROWS + idx] = v;
        }
    }
    __syncthreads();

    int w = tid >> 5, lane = tid & 31;

    // Stage 1: warp w -> anchor (w&15), row-half (w>>4). Top-8 of 512 values.
    {
        int t = w & 15, hh = w >> 4;
        int* rowp = sh_dist + t * CROWS + hh * 512;
        #pragma unroll 1
        for (int it = 0; it < KSEL; it++) {
            int m = 0x7fffffff;
            #pragma unroll
            for (int k = 0; k < 4; k++) {
                int4 v = *(const int4*)&rowp[4 * lane + 128 * k];
                m = min(m, min(min(v.x, v.y), min(v.z, v.w)));
            }
            m = (int)__reduce_min_sync(0xffffffffu, (uint)m);
            if (lane == 0) sh_cand[(t * 2 + hh) * KSEL + it] = m;
            int idx = m & 1023;                    // local-row idx (global in chunk)
            int loc = idx - hh * 512;              // offset within this half
            if (((loc >> 2) & 31) == lane) rowp[loc] = 0x7fffffff;
            __syncwarp();
        }
    }
    __syncthreads();

    // Stage 2: warps 0-15 merge the 16 candidates of anchor w -> final top-8.
    if (w < TA) {
        uint v = (lane < 2 * KSEL) ? (uint)sh_cand[(w * 2 + (lane >> 3)) * KSEL + (lane & 7)]
                                   : 0xffffffffu;
        int aglob = tile * TA + w;
        #pragma unroll 1
        for (int it = 0; it < KSEL; it++) {
            uint m = __reduce_min_sync(0xffffffffu, v);
            if (lane == 0)
                g_candi[side][aglob][chunk * KSEL + it] = nb + (int)(m & 1023u);
            if (v == m) v = 0xffffffffu;   // packed values unique (idx bits)
        }
    }
}

// ---------------------------------------------------------------------------
// Exact fp32 repair: one THREAD per candidate (high MLP), then warp-0 top-10.
// ---------------------------------------------------------------------------
#define NCAND (NCHUNK * KSEL)   // 160
__global__ void __launch_bounds__(256) k_exact(const float* __restrict__ out1,
                                               const float* __restrict__ out2) {
    int a = blockIdx.x;               // 0..2047
    int side = a >> 10, ai = a & (NA - 1);
    int tid = threadIdx.x, lane = tid & 31;
    __shared__ __align__(16) float4 sh_a4[D / 4];
    __shared__ float sh_dv[NCAND];

    if (tid < D / 4) sh_a4[tid] = ((const float4*)g_anch[side][ai])[tid];
    __syncthreads();

    if (tid < NCAND) {
        int ix = g_candi[side][ai][tid];
        const float* db = side ? out1 : out2;
        const float4* rp = (const float4*)(db + (size_t)ix * D);
        float s0 = 0.f, s1 = 0.f, s2 = 0.f, s3 = 0.f;
        #pragma unroll 8
        for (int j = 0; j < D / 4; j++) {
            float4 bv = rp[j];
            float4 av = sh_a4[j];
            s0 += fabsf(av.x - bv.x);
            s1 += fabsf(av.y - bv.y);
            s2 += fabsf(av.z - bv.z);
            s3 += fabsf(av.w - bv.w);
        }
        sh_dv[tid] = (s0 + s1) + (s2 + s3);
    }
    __syncthreads();

    if (tid < 32) {
        // lane holds 5 values (stride 32); nonneg floats order as uint bits.
        float v[5];
        #pragma unroll
        for (int k = 0; k < 5; k++) v[k] = sh_dv[lane + 32 * k];
        const float INF = __int_as_float(0x7f800000);
        float Dm = g_Dm[ai];
        float loss = 0.0f;
        #pragma unroll 1
        for (int it = 0; it < KTOP; it++) {
            uint mb = 0xffffffffu;
            #pragma unroll
            for (int k = 0; k < 5; k++) mb = min(mb, __float_as_uint(v[k]));
            mb = __reduce_min_sync(0xffffffffu, mb);
            float m = __uint_as_float(mb);
            loss += fmaxf(0.0f, Dm - m);
            // remove exactly one copy of m (ballot-elected leader lane)
            bool have = (v[0] == m) | (v[1] == m) | (v[2] == m) |
                        (v[3] == m) | (v[4] == m);
            uint msk = __ballot_sync(0xffffffffu, have);
            if (lane == (int)(__ffs(msk) - 1)) {
                if      (v[0] == m) v[0] = INF;
                else if (v[1] == m) v[1] = INF;
                else if (v[2] == m) v[2] = INF;
                else if (v[3] == m) v[3] = INF;
                else                v[4] = INF;
            }
        }
        if (lane == 0) g_partial[a] = loss;
    }
}

// ---------------------------------------------------------------------------
// Deterministic final reduction: 2048 partials -> scalar / (A*K)
// ---------------------------------------------------------------------------
__global__ void k_final(float* __restrict__ out) {
    __shared__ float s[512];
    int tid = threadIdx.x;   // 1024 threads; 512 float4 elements total
    float v = 0.0f;
    if (tid < 512) {
        float4 p = ((const float4*)g_partial)[tid];
        v = (p.x + p.y) + (p.z + p.w);
        s[tid] = v;
    }
    __syncthreads();
    for (int st = 256; st; st >>= 1) {
        if (tid < st) s[tid] += s[tid + st];
        __syncthreads();
    }
    if (tid == 0) out[0] = s[0] / (float)(NA * KTOP);
}

// ---------------------------------------------------------------------------
extern "C" void kernel_launch(void* const* d_in, const int* in_sizes, int n_in,
                              void* d_out, int out_size) {
    const float* out1 = (const float*)d_in[0];
    const float* out2 = (const float*)d_in[1];
    const int*   an1  = (const int*)d_in[2];
    const int*   an2  = (const int*)d_in[3];
    float* out = (float*)d_out;

    // Idempotent, capture-legal (no alloc, no sync): raise dynamic smem cap.
    cudaFuncSetAttribute(k_dist, cudaFuncAttributeMaxDynamicSharedMemorySize,
                         SM_TOTAL);

    k_prep<<<2 * QB + NA / 2, 256>>>(out1, out2, an1, an2);
    k_dist<<<dim3(NA / TA, NCHUNK, 2), 1024, SM_TOTAL>>>();
    k_exact<<<2 * NA, 256>>>(out1, out2);
    k_final<<<1, 1024>>>(out);
}

// round 13
// speedup vs baseline: 1.0441x; 1.0441x over previous
#include <cuda_runtime.h>
#include <cstdint>

#define D       128
#define NROWS   20000
#define NPAD    20480
#define NA      1024
#define TA      8         // anchors per CTA
#define CROWS   1024
#define NCHUNK  20
#define KSEL    8
#define KTOP    10
#define GAMMA   1.0f
#define SCALE   25.4f     // int8 quant scale, selection-only
#define QBLK    625       // quant blocks per side (625*32 = 20000 exactly)

typedef unsigned int uint;

// Static device scratch (allocation-free rule: __device__ globals only)
__device__ __align__(16) uint g_qT[2][D / 4][NPAD];     // transposed packed DB
__device__ __align__(16) uint g_anchq[2][NA][D / 4];    // packed quantized anchors
__device__ __align__(16) float g_anch[2][NA][D];        // fp32 anchors
__device__ float g_Dm[NA];                              // positive dist + gamma
__device__ int   g_candi[2][NA][NCHUNK * KSEL];         // candidate row indices
__device__ float g_partial[2 * NA];                     // per-anchor loss
__device__ uint  g_done;                                // last-block counter

// Fused SAD-accumulate: acc += sum_bytes(|s8(a) - s8(b)|)  (single SASS op)
__device__ __forceinline__ void sad4(uint& acc, uint a, uint b) {
    asm("vabsdiff4.u32.s32.s32.add %0, %1, %2, %0;" : "+r"(acc) : "r"(a), "r"(b));
}

// ---------------------------------------------------------------------------
// Prep: quantize+transpose DBs with coalesced smem transpose (blocks
// 0..2*QBLK-1, 32 rows each), then gather anchors (2 per block).
// Also resets g_done for the k_exact last-block reduction.
// ---------------------------------------------------------------------------
__global__ void k_prep(const float* __restrict__ out1,
                       const float* __restrict__ out2,
                       const int* __restrict__ an1,
                       const int* __restrict__ an2) {
    int b = blockIdx.x;
    int tid = threadIdx.x;
    if (b == 0 && tid == 0) g_done = 0;

    if (b < 2 * QBLK) {
        int side = (b >= QBLK);
        int r0 = (side ? b - QBLK : b) * 32;
        const float* src = side ? out1 : out2;
        __shared__ unsigned char qb[32][132];   // 132-byte pad: conflict-free
        // Coalesced load + quantize: 32 rows x 128 floats.
        #pragma unroll
        for (int k = 0; k < 16; k++) {
            int idx = tid + k * 256;            // 0..4095
            int row = idx >> 7, dim = idx & 127;
            float v = src[(size_t)(r0 + row) * D + dim];
            int q = __float2int_rn(fminf(fmaxf(v * SCALE, -127.f), 127.f));
            qb[row][dim] = (unsigned char)q;
        }
        __syncthreads();
        // Transposed write: warp covers 32 consecutive rows (lane = row).
        int lane = tid & 31, wj = tid >> 5;
        #pragma unroll
        for (int k = 0; k < 4; k++) {
            int j = wj + 8 * k;
            uint p = *(const uint*)&qb[lane][4 * j];   // dims 4j..4j+3 packed
            g_qT[side][j][r0 + lane] = p;              // coalesced over lanes
        }
        return;
    }
    // gather: 2 anchors per block, 128 threads each
    int i = (b - 2 * QBLK) * 2 + (tid >> 7);
    int d = tid & 127;
    float v1 = out1[(size_t)an1[i] * D + d];
    float v2 = out2[(size_t)an2[i] * D + d];
    g_anch[0][i][d] = v1;
    g_anch[1][i][d] = v2;
    int q1 = __float2int_rn(fminf(fmaxf(v1 * SCALE, -127.f), 127.f)) & 255;
    int q2 = __float2int_rn(fminf(fmaxf(v2 * SCALE, -127.f), 127.f)) & 255;
    __shared__ unsigned char b1[2][D], b2[2][D];
    int h = tid >> 7;
    b1[h][d] = (unsigned char)q1;
    b2[h][d] = (unsigned char)q2;
    __syncthreads();
    if (d < D / 4) {
        g_anchq[0][i][d] = ((const uint*)b1[h])[d];
        g_anchq[1][i][d] = ((const uint*)b2[h])[d];
    }
    float x = fabsf(v1 - v2);
    #pragma unroll
    for (int off = 16; off; off >>= 1) x += __shfl_down_sync(0xffffffffu, x, off);
    __shared__ float ws[8];
    if ((tid & 31) == 0) ws[tid >> 5] = x;
    __syncthreads();
    if (d == 0) g_Dm[i] = ws[4 * h] + ws[4 * h + 1] + ws[4 * h + 2] + ws[4 * h + 3] + GAMMA;
}

// ---------------------------------------------------------------------------
// int8 SAD distances + per-chunk top-8 selection (two-stage, 16 warps).
// Grid (128 tiles, 10 chunk-pairs, 2 sides), 512 threads, 2 CTAs/SM.
// Each CTA processes 2 chunks (halves scheduler wave count). Mainloop and
// selection byte-identical to the proven round-11 kernel.
// ---------------------------------------------------------------------------
__global__ void __launch_bounds__(512, 2) k_dist() {
    int tile  = blockIdx.x;
    int cpair = blockIdx.y;
    int side  = blockIdx.z;
    int tid = threadIdx.x;
    int half = tid >> 8;          // anchor group: 0 -> anchors 0-3, 1 -> 4-7
    int pos  = tid & 255;

    __shared__ __align__(16) uint sh_aq[TA][D / 4];  // 1 KB
    __shared__ __align__(16) int sh_dist[TA][CROWS]; // 32 KB packed dists
    __shared__ int sh_cand[TA][2][KSEL];             // stage-1 candidates

    if (tid < TA * (D / 4)) {
        int t = tid >> 5, j = tid & 31;
        sh_aq[t][j] = g_anchq[side][tile * TA + t][j];
    }
    __syncthreads();

    const int p2 = 2 * pos;       // local rows p2, p2+1, p2+512, p2+513
    const int ta0 = half * 4;
    int w = tid >> 5, lane = tid & 31;

    #pragma unroll 1
    for (int cc = 0; cc < 2; cc++) {
        int chunk = 2 * cpair + cc;
        const uint* __restrict__ qp = &g_qT[side][0][0] + chunk * CROWS + p2;

        uint acc[4][4];
        #pragma unroll
        for (int t = 0; t < 4; t++)
            #pragma unroll
            for (int r = 0; r < 4; r++) acc[t][r] = 0;

        #pragma unroll
        for (int jb = 0; jb < 8; jb++) {
            uint4 a0 = *(const uint4*)&sh_aq[ta0 + 0][4 * jb];
            uint4 a1 = *(const uint4*)&sh_aq[ta0 + 1][4 * jb];
            uint4 a2 = *(const uint4*)&sh_aq[ta0 + 2][4 * jb];
            uint4 a3 = *(const uint4*)&sh_aq[ta0 + 3][4 * jb];
            #pragma unroll
            for (int jj = 0; jj < 4; jj++) {
                int j = 4 * jb + jj;
                uint2 bA = *(const uint2*)(qp + (size_t)j * NPAD);        // p2,p2+1
                uint2 bB = *(const uint2*)(qp + (size_t)j * NPAD + 512);  // +512,+513
                uint av0 = jj == 0 ? a0.x : jj == 1 ? a0.y : jj == 2 ? a0.z : a0.w;
                uint av1 = jj == 0 ? a1.x : jj == 1 ? a1.y : jj == 2 ? a1.z : a1.w;
                uint av2 = jj == 0 ? a2.x : jj == 1 ? a2.y : jj == 2 ? a2.z : a2.w;
                uint av3 = jj == 0 ? a3.x : jj == 1 ? a3.y : jj == 2 ? a3.z : a3.w;
                sad4(acc[0][0], av0, bA.x);
                sad4(acc[0][1], av0, bA.y);
                sad4(acc[0][2], av0, bB.x);
                sad4(acc[0][3], av0, bB.y);
                sad4(acc[1][0], av1, bA.x);
                sad4(acc[1][1], av1, bA.y);
                sad4(acc[1][2], av1, bB.x);
                sad4(acc[1][3], av1, bB.y);
                sad4(acc[2][0], av2, bA.x);
                sad4(acc[2][1], av2, bA.y);
                sad4(acc[2][2], av2, bB.x);
                sad4(acc[2][3], av2, bB.y);
                sad4(acc[3][0], av3, bA.x);
                sad4(acc[3][1], av3, bA.y);
                sad4(acc[3][2], av3, bB.x);
                sad4(acc[3][3], av3, bB.y);
            }
        }

        // Store packed (sad<<10 | idx); invalid rows -> INT_MAX.
        const int nb = chunk * CROWS;
        #pragma unroll
        for (int r = 0; r < 4; r++) {
            int idx = (r & 1) + ((r >> 1) << 9) + p2;   // p2,p2+1,p2+512,p2+513
            bool valid = (nb + idx) < NROWS;
            #pragma unroll
            for (int t = 0; t < 4; t++) {
                int v = valid ? (int)((acc[t][r] << 10) | (uint)idx) : 0x7fffffff;
                sh_dist[ta0 + t][idx] = v;
            }
        }
        __syncthreads();   // also orders previous iteration's stage 2

        // Stage 1: warp w -> anchor (w&7), row-half (w>>3). Top-8 of 512.
        {
            int t = w & 7, hh = w >> 3;
            int* rowp = &sh_dist[t][hh * 512];
            #pragma unroll 1
            for (int it = 0; it < KSEL; it++) {
                int m = 0x7fffffff;
                #pragma unroll
                for (int k = 0; k < 4; k++) {
                    int4 v = *(const int4*)&rowp[4 * lane + 128 * k];
                    m = min(m, min(min(v.x, v.y), min(v.z, v.w)));
                }
                m = (int)__reduce_min_sync(0xffffffffu, (uint)m);
                if (lane == 0) sh_cand[t][hh][it] = m;
                int idx = m & 1023;
                int loc = idx - hh * 512;
                if (((loc >> 2) & 31) == lane) rowp[loc] = 0x7fffffff;
                __syncwarp();
            }
        }
        __syncthreads();

        // Stage 2: warps 0-7 merge 16 candidates of anchor w -> top-8.
        if (w < TA) {
            uint v = (lane < 2 * KSEL) ? (uint)sh_cand[w][lane >> 3][lane & 7]
                                       : 0xffffffffu;
            int aglob = tile * TA + w;
            #pragma unroll 1
            for (int it = 0; it < KSEL; it++) {
                uint m = __reduce_min_sync(0xffffffffu, v);
                if (lane == 0)
                    g_candi[side][aglob][chunk * KSEL + it] = nb + (int)(m & 1023u);
                if (v == m) v = 0xffffffffu;   // packed values unique (idx bits)
            }
        }
    }
}

// ---------------------------------------------------------------------------
// Exact fp32 repair + fused deterministic final reduction (last-block).
// One THREAD per candidate (high MLP), warp-0 top-10, then the last block
// to finish sums g_partial in a FIXED order (bit-deterministic).
// ---------------------------------------------------------------------------
#define NCAND (NCHUNK * KSEL)   // 160
__global__ void __launch_bounds__(256) k_exact(const float* __restrict__ out1,
                                               const float* __restrict__ out2,
                                               float* __restrict__ out) {
    int a = blockIdx.x;               // 0..2047
    int side = a >> 10, ai = a & (NA - 1);
    int tid = threadIdx.x, lane = tid & 31;
    __shared__ __align__(16) float4 sh_a4[D / 4];
    __shared__ float sh_dv[NCAND];
    __shared__ float s[256];
    __shared__ bool amLast;

    if (tid < D / 4) sh_a4[tid] = ((const float4*)g_anch[side][ai])[tid];
    __syncthreads();

    if (tid < NCAND) {
        int ix = g_candi[side][ai][tid];
        const float* db = side ? out1 : out2;
        const float4* rp = (const float4*)(db + (size_t)ix * D);
        float s0 = 0.f, s1 = 0.f, s2 = 0.f, s3 = 0.f;
        #pragma unroll 8
        for (int j = 0; j < D / 4; j++) {
            float4 bv = rp[j];
            float4 av = sh_a4[j];
            s0 += fabsf(av.x - bv.x);
            s1 += fabsf(av.y - bv.y);
            s2 += fabsf(av.z - bv.z);
            s3 += fabsf(av.w - bv.w);
        }
        sh_dv[tid] = (s0 + s1) + (s2 + s3);
    }
    __syncthreads();

    if (tid < 32) {
        // lane holds 5 values (stride 32); nonneg floats order as uint bits.
        float v[5];
        #pragma unroll
        for (int k = 0; k < 5; k++) v[k] = sh_dv[lane + 32 * k];
        const float INF = __int_as_float(0x7f800000);
        float Dm = g_Dm[ai];
        float loss = 0.0f;
        #pragma unroll 1
        for (int it = 0; it < KTOP; it++) {
            uint mb = 0xffffffffu;
            #pragma unroll
            for (int k = 0; k < 5; k++) mb = min(mb, __float_as_uint(v[k]));
            mb = __reduce_min_sync(0xffffffffu, mb);
            float m = __uint_as_float(mb);
            loss += fmaxf(0.0f, Dm - m);
            bool have = (v[0] == m) | (v[1] == m) | (v[2] == m) |
                        (v[3] == m) | (v[4] == m);
            uint msk = __ballot_sync(0xffffffffu, have);
            if (lane == (int)(__ffs(msk) - 1)) {
                if      (v[0] == m) v[0] = INF;
                else if (v[1] == m) v[1] = INF;
                else if (v[2] == m) v[2] = INF;
                else if (v[3] == m) v[3] = INF;
                else                v[4] = INF;
            }
        }
        if (lane == 0) g_partial[a] = loss;
    }

    // Last-block deterministic final reduction.
    __syncthreads();
    __threadfence();                               // release g_partial[a]
    if (tid == 0) amLast = (atomicAdd(&g_done, 1u) == 2u * NA - 1u);
    __syncthreads();
    if (amLast) {
        __threadfence();                           // acquire all g_partial
        float v = 0.0f;
        #pragma unroll
        for (int k = 0; k < 8; k++) v += g_partial[tid + 256 * k];  // fixed order
        s[tid] = v;
        __syncthreads();
        for (int st = 128; st; st >>= 1) {
            if (tid < st) s[tid] += s[tid + st];
            __syncthreads();
        }
        if (tid == 0) out[0] = s[0] / (float)(NA * KTOP);
    }
}

// ---------------------------------------------------------------------------
extern "C" void kernel_launch(void* const* d_in, const int* in_sizes, int n_in,
                              void* d_out, int out_size) {
    const float* out1 = (const float*)d_in[0];
    const float* out2 = (const float*)d_in[1];
    const int*   an1  = (const int*)d_in[2];
    const int*   an2  = (const int*)d_in[3];
    float* out = (float*)d_out;

    k_prep<<<2 * QBLK + NA / 2, 256>>>(out1, out2, an1, an2);
    k_dist<<<dim3(NA / TA, NCHUNK / 2, 2), 512>>>();
    k_exact<<<2 * NA, 256>>>(out1, out2, out);
}

// round 15
// speedup vs baseline: 1.0935x; 1.0474x over previous
#include <cuda_runtime.h>
#include <cstdint>

#define D       128
#define NROWS   20000
#define NPAD    20480
#define NA      1024
#define TA      8         // anchors per CTA
#define CROWS   1024
#define NCHUNK  20
#define KSEL    8
#define KTOP    10
#define GAMMA   1.0f
#define SCALE   25.4f     // int8 quant scale, selection-only
#define QBLK    625       // quant blocks per side (625*32 = 20000 exactly)

typedef unsigned int uint;

// Static device scratch (allocation-free rule: __device__ globals only)
__device__ __align__(16) uint g_qT[2][D / 4][NPAD];     // transposed packed DB
__device__ __align__(16) uint g_anchq[2][NA][D / 4];    // packed quantized anchors
__device__ __align__(16) float g_anch[2][NA][D];        // fp32 anchors
__device__ float g_Dm[NA];                              // positive dist + gamma
__device__ int   g_candi[2][NA][NCHUNK * KSEL];         // candidate row indices
__device__ float g_partial[2 * NA];                     // per-anchor loss
__device__ uint  g_done;                                // last-block counter

// Fused SAD-accumulate: acc += sum_bytes(|s8(a) - s8(b)|)  (single SASS op)
__device__ __forceinline__ void sad4(uint& acc, uint a, uint b) {
    asm("vabsdiff4.u32.s32.s32.add %0, %1, %2, %0;" : "+r"(acc) : "r"(a), "r"(b));
}

// ---------------------------------------------------------------------------
// Prep (r13, measured 8us): quantize+transpose DBs via coalesced smem
// transpose (32 rows/block), then gather anchors (2/block). Resets g_done.
// ---------------------------------------------------------------------------
__global__ void k_prep(const float* __restrict__ out1,
                       const float* __restrict__ out2,
                       const int* __restrict__ an1,
                       const int* __restrict__ an2) {
    int b = blockIdx.x;
    int tid = threadIdx.x;
    if (b == 0 && tid == 0) g_done = 0;

    if (b < 2 * QBLK) {
        int side = (b >= QBLK);
        int r0 = (side ? b - QBLK : b) * 32;
        const float* src = side ? out1 : out2;
        __shared__ unsigned char qb[32][132];   // 132-byte pad: conflict-free
        #pragma unroll
        for (int k = 0; k < 16; k++) {
            int idx = tid + k * 256;            // 0..4095
            int row = idx >> 7, dim = idx & 127;
            float v = src[(size_t)(r0 + row) * D + dim];
            int q = __float2int_rn(fminf(fmaxf(v * SCALE, -127.f), 127.f));
            qb[row][dim] = (unsigned char)q;
        }
        __syncthreads();
        int lane = tid & 31, wj = tid >> 5;
        #pragma unroll
        for (int k = 0; k < 4; k++) {
            int j = wj + 8 * k;
            uint p = *(const uint*)&qb[lane][4 * j];   // dims 4j..4j+3 packed
            g_qT[side][j][r0 + lane] = p;              // coalesced over lanes
        }
        return;
    }
    // gather: 2 anchors per block, 128 threads each
    int i = (b - 2 * QBLK) * 2 + (tid >> 7);
    int d = tid & 127;
    float v1 = out1[(size_t)an1[i] * D + d];
    float v2 = out2[(size_t)an2[i] * D + d];
    g_anch[0][i][d] = v1;
    g_anch[1][i][d] = v2;
    int q1 = __float2int_rn(fminf(fmaxf(v1 * SCALE, -127.f), 127.f)) & 255;
    int q2 = __float2int_rn(fminf(fmaxf(v2 * SCALE, -127.f), 127.f)) & 255;
    __shared__ unsigned char b1[2][D], b2[2][D];
    int h = tid >> 7;
    b1[h][d] = (unsigned char)q1;
    b2[h][d] = (unsigned char)q2;
    __syncthreads();
    if (d < D / 4) {
        g_anchq[0][i][d] = ((const uint*)b1[h])[d];
        g_anchq[1][i][d] = ((const uint*)b2[h])[d];
    }
    float x = fabsf(v1 - v2);
    #pragma unroll
    for (int off = 16; off; off >>= 1) x += __shfl_down_sync(0xffffffffu, x, off);
    __shared__ float ws[8];
    if ((tid & 31) == 0) ws[tid >> 5] = x;
    __syncthreads();
    if (d == 0) g_Dm[i] = ws[4 * h] + ws[4 * h + 1] + ws[4 * h + 2] + ws[4 * h + 3] + GAMMA;
}

// ---------------------------------------------------------------------------
// int8 SAD distances + per-chunk top-8 selection (r11, proven shape).
// Grid (128 tiles, 20 chunks, 2 sides), 512 threads, 2 CTAs/SM.
// ---------------------------------------------------------------------------
__global__ void __launch_bounds__(512, 2) k_dist() {
    int tile  = blockIdx.x;
    int chunk = blockIdx.y;
    int side  = blockIdx.z;
    int tid = threadIdx.x;
    int half = tid >> 8;          // anchor group: 0 -> anchors 0-3, 1 -> 4-7
    int pos  = tid & 255;

    __shared__ __align__(16) uint sh_aq[TA][D / 4];  // 1 KB
    __shared__ __align__(16) int sh_dist[TA][CROWS]; // 32 KB packed dists
    __shared__ int sh_cand[TA][2][KSEL];             // stage-1 candidates

    if (tid < TA * (D / 4)) {
        int t = tid >> 5, j = tid & 31;
        sh_aq[t][j] = g_anchq[side][tile * TA + t][j];
    }
    __syncthreads();

    uint acc[4][4];
    #pragma unroll
    for (int t = 0; t < 4; t++)
        #pragma unroll
        for (int r = 0; r < 4; r++) acc[t][r] = 0;

    const int p2 = 2 * pos;       // local rows p2, p2+1, p2+512, p2+513
    const uint* __restrict__ qp = &g_qT[side][0][0] + chunk * CROWS + p2;
    const int ta0 = half * 4;

    #pragma unroll
    for (int jb = 0; jb < 8; jb++) {
        uint4 a0 = *(const uint4*)&sh_aq[ta0 + 0][4 * jb];
        uint4 a1 = *(const uint4*)&sh_aq[ta0 + 1][4 * jb];
        uint4 a2 = *(const uint4*)&sh_aq[ta0 + 2][4 * jb];
        uint4 a3 = *(const uint4*)&sh_aq[ta0 + 3][4 * jb];
        #pragma unroll
        for (int jj = 0; jj < 4; jj++) {
            int j = 4 * jb + jj;
            uint2 bA = *(const uint2*)(qp + (size_t)j * NPAD);        // p2,p2+1
            uint2 bB = *(const uint2*)(qp + (size_t)j * NPAD + 512);  // +512,+513
            uint av0 = jj == 0 ? a0.x : jj == 1 ? a0.y : jj == 2 ? a0.z : a0.w;
            uint av1 = jj == 0 ? a1.x : jj == 1 ? a1.y : jj == 2 ? a1.z : a1.w;
            uint av2 = jj == 0 ? a2.x : jj == 1 ? a2.y : jj == 2 ? a2.z : a2.w;
            uint av3 = jj == 0 ? a3.x : jj == 1 ? a3.y : jj == 2 ? a3.z : a3.w;
            sad4(acc[0][0], av0, bA.x);
            sad4(acc[0][1], av0, bA.y);
            sad4(acc[0][2], av0, bB.x);
            sad4(acc[0][3], av0, bB.y);
            sad4(acc[1][0], av1, bA.x);
            sad4(acc[1][1], av1, bA.y);
            sad4(acc[1][2], av1, bB.x);
            sad4(acc[1][3], av1, bB.y);
            sad4(acc[2][0], av2, bA.x);
            sad4(acc[2][1], av2, bA.y);
            sad4(acc[2][2], av2, bB.x);
            sad4(acc[2][3], av2, bB.y);
            sad4(acc[3][0], av3, bA.x);
            sad4(acc[3][1], av3, bA.y);
            sad4(acc[3][2], av3, bB.x);
            sad4(acc[3][3], av3, bB.y);
        }
    }

    // Store packed (sad<<10 | idx); invalid rows -> INT_MAX.
    const int nb = chunk * CROWS;
    #pragma unroll
    for (int r = 0; r < 4; r++) {
        int idx = (r & 1) + ((r >> 1) << 9) + p2;   // p2, p2+1, p2+512, p2+513
        bool valid = (nb + idx) < NROWS;
        #pragma unroll
        for (int t = 0; t < 4; t++) {
            int v = valid ? (int)((acc[t][r] << 10) | (uint)idx) : 0x7fffffff;
            sh_dist[ta0 + t][idx] = v;
        }
    }
    __syncthreads();

    int w = tid >> 5, lane = tid & 31;

    // Stage 1: warp w -> anchor (w&7), row-half (w>>3). Top-8 of 512 values.
    {
        int t = w & 7, hh = w >> 3;
        int* rowp = &sh_dist[t][hh * 512];
        #pragma unroll 1
        for (int it = 0; it < KSEL; it++) {
            int m = 0x7fffffff;
            #pragma unroll
            for (int k = 0; k < 4; k++) {
                int4 v = *(const int4*)&rowp[4 * lane + 128 * k];
                m = min(m, min(min(v.x, v.y), min(v.z, v.w)));
            }
            m = (int)__reduce_min_sync(0xffffffffu, (uint)m);
            if (lane == 0) sh_cand[t][hh][it] = m;
            int idx = m & 1023;
            int loc = idx - hh * 512;
            if (((loc >> 2) & 31) == lane) rowp[loc] = 0x7fffffff;
            __syncwarp();
        }
    }
    __syncthreads();

    // Stage 2: warps 0-7 merge the 16 candidates of anchor w -> final top-8.
    if (w < TA) {
        uint v = (lane < 2 * KSEL) ? (uint)sh_cand[w][lane >> 3][lane & 7]
                                   : 0xffffffffu;
        int aglob = tile * TA + w;
        #pragma unroll 1
        for (int it = 0; it < KSEL; it++) {
            uint m = __reduce_min_sync(0xffffffffu, v);
            if (lane == 0)
                g_candi[side][aglob][chunk * KSEL + it] = nb + (int)(m & 1023u);
            if (v == m) v = 0xffffffffu;   // packed values unique (idx bits)
        }
    }
}

// ---------------------------------------------------------------------------
// Exact fp32 repair + fused deterministic final reduction (last-block).
// ---------------------------------------------------------------------------
#define NCAND (NCHUNK * KSEL)   // 160
__global__ void __launch_bounds__(256) k_exact(const float* __restrict__ out1,
                                               const float* __restrict__ out2,
                                               float* __restrict__ out) {
    int a = blockIdx.x;               // 0..2047
    int side = a >> 10, ai = a & (NA - 1);
    int tid = threadIdx.x, lane = tid & 31;
    __shared__ __align__(16) float4 sh_a4[D / 4];
    __shared__ float sh_dv[NCAND];
    __shared__ float s[256];
    __shared__ bool amLast;

    if (tid < D / 4) sh_a4[tid] = ((const float4*)g_anch[side][ai])[tid];
    __syncthreads();

    if (tid < NCAND) {
        int ix = g_candi[side][ai][tid];
        const float* db = side ? out1 : out2;
        const float4* rp = (const float4*)(db + (size_t)ix * D);
        float s0 = 0.f, s1 = 0.f, s2 = 0.f, s3 = 0.f;
        #pragma unroll 8
        for (int j = 0; j < D / 4; j++) {
            float4 bv = rp[j];
            float4 av = sh_a4[j];
            s0 += fabsf(av.x - bv.x);
            s1 += fabsf(av.y - bv.y);
            s2 += fabsf(av.z - bv.z);
            s3 += fabsf(av.w - bv.w);
        }
        sh_dv[tid] = (s0 + s1) + (s2 + s3);
    }
    __syncthreads();

    if (tid < 32) {
        // lane holds 5 values (stride 32); nonneg floats order as uint bits.
        float v[5];
        #pragma unroll
        for (int k = 0; k < 5; k++) v[k] = sh_dv[lane + 32 * k];
        const float INF = __int_as_float(0x7f800000);
        float Dm = g_Dm[ai];
        float loss = 0.0f;
        #pragma unroll 1
        for (int it = 0; it < KTOP; it++) {
            uint mb = 0xffffffffu;
            #pragma unroll
            for (int k = 0; k < 5; k++) mb = min(mb, __float_as_uint(v[k]));
            mb = __reduce_min_sync(0xffffffffu, mb);
            float m = __uint_as_float(mb);
            loss += fmaxf(0.0f, Dm - m);
            bool have = (v[0] == m) | (v[1] == m) | (v[2] == m) |
                        (v[3] == m) | (v[4] == m);
            uint msk = __ballot_sync(0xffffffffu, have);
            if (lane == (int)(__ffs(msk) - 1)) {
                if      (v[0] == m) v[0] = INF;
                else if (v[1] == m) v[1] = INF;
                else if (v[2] == m) v[2] = INF;
                else if (v[3] == m) v[3] = INF;
                else                v[4] = INF;
            }
        }
        if (lane == 0) g_partial[a] = loss;
    }

    // Last-block deterministic final reduction.
    __syncthreads();
    __threadfence();                               // release g_partial[a]
    if (tid == 0) amLast = (atomicAdd(&g_done, 1u) == 2u * NA - 1u);
    __syncthreads();
    if (amLast) {
        __threadfence();                           // acquire all g_partial
        float v = 0.0f;
        #pragma unroll
        for (int k = 0; k < 8; k++) v += g_partial[tid + 256 * k];  // fixed order
        s[tid] = v;
        __syncthreads();
        for (int st = 128; st; st >>= 1) {
            if (tid < st) s[tid] += s[tid + st];
            __syncthreads();
        }
        if (tid == 0) out[0] = s[0] / (float)(NA * KTOP);
    }
}

// ---------------------------------------------------------------------------
extern "C" void kernel_launch(void* const* d_in, const int* in_sizes, int n_in,
                              void* d_out, int out_size) {
    const float* out1 = (const float*)d_in[0];
    const float* out2 = (const float*)d_in[1];
    const int*   an1  = (const int*)d_in[2];
    const int*   an2  = (const int*)d_in[3];
    float* out = (float*)d_out;

    k_prep<<<2 * QBLK + NA / 2, 256>>>(out1, out2, an1, an2);
    k_dist<<<dim3(NA / TA, NCHUNK, 2), 512>>>();
    k_exact<<<2 * NA, 256>>>(out1, out2, out);
}

// round 16
// speedup vs baseline: 1.1290x; 1.0324x over previous
#include <cuda_runtime.h>
#include <cstdint>

#define D       128
#define NROWS   20000
#define NPAD    20480
#define NA      1024
#define TA      8         // anchors per CTA
#define CROWS   1024
#define NCHUNK  20
#define KSEL    8
#define KTOP    10
#define GAMMA   1.0f
#define SCALE   25.4f     // int8 quant scale, selection-only
#define QBLK    625       // quant blocks per side (625*32 = 20000 exactly)

typedef unsigned int uint;

// Static device scratch (allocation-free rule: __device__ globals only)
__device__ __align__(16) uint g_qT[2][D / 4][NPAD];     // transposed packed DB
__device__ __align__(16) uint g_anchq[2][NA][D / 4];    // packed quantized anchors
__device__ __align__(16) float g_anch[2][NA][D];        // fp32 anchors
__device__ float g_Dm[NA];                              // positive dist + gamma
__device__ int   g_candi[2][NA][NCHUNK * KSEL];         // candidate row indices
__device__ float g_partial[2 * NA];                     // per-anchor loss
__device__ uint  g_done;                                // last-block counter

// Fused SAD-accumulate: acc += sum_bytes(|s8(a) - s8(b)|)  (single SASS op)
__device__ __forceinline__ void sad4(uint& acc, uint a, uint b) {
    asm("vabsdiff4.u32.s32.s32.add %0, %1, %2, %0;" : "+r"(acc) : "r"(a), "r"(b));
}

// ---------------------------------------------------------------------------
// Prep (measured 8us): quantize+transpose DBs via coalesced smem transpose
// (32 rows/block), then gather anchors (2/block). Resets g_done.
// ---------------------------------------------------------------------------
__global__ void k_prep(const float* __restrict__ out1,
                       const float* __restrict__ out2,
                       const int* __restrict__ an1,
                       const int* __restrict__ an2) {
    int b = blockIdx.x;
    int tid = threadIdx.x;
    if (b == 0 && tid == 0) g_done = 0;

    if (b < 2 * QBLK) {
        int side = (b >= QBLK);
        int r0 = (side ? b - QBLK : b) * 32;
        const float* src = side ? out1 : out2;
        __shared__ unsigned char qb[32][132];   // 132-byte pad: conflict-free
        #pragma unroll
        for (int k = 0; k < 16; k++) {
            int idx = tid + k * 256;            // 0..4095
            int row = idx >> 7, dim = idx & 127;
            float v = src[(size_t)(r0 + row) * D + dim];
            int q = __float2int_rn(fminf(fmaxf(v * SCALE, -127.f), 127.f));
            qb[row][dim] = (unsigned char)q;
        }
        __syncthreads();
        int lane = tid & 31, wj = tid >> 5;
        #pragma unroll
        for (int k = 0; k < 4; k++) {
            int j = wj + 8 * k;
            uint p = *(const uint*)&qb[lane][4 * j];   // dims 4j..4j+3 packed
            g_qT[side][j][r0 + lane] = p;              // coalesced over lanes
        }
        return;
    }
    // gather: 2 anchors per block, 128 threads each
    int i = (b - 2 * QBLK) * 2 + (tid >> 7);
    int d = tid & 127;
    float v1 = out1[(size_t)an1[i] * D + d];
    float v2 = out2[(size_t)an2[i] * D + d];
    g_anch[0][i][d] = v1;
    g_anch[1][i][d] = v2;
    int q1 = __float2int_rn(fminf(fmaxf(v1 * SCALE, -127.f), 127.f)) & 255;
    int q2 = __float2int_rn(fminf(fmaxf(v2 * SCALE, -127.f), 127.f)) & 255;
    __shared__ unsigned char b1[2][D], b2[2][D];
    int h = tid >> 7;
    b1[h][d] = (unsigned char)q1;
    b2[h][d] = (unsigned char)q2;
    __syncthreads();
    if (d < D / 4) {
        g_anchq[0][i][d] = ((const uint*)b1[h])[d];
        g_anchq[1][i][d] = ((const uint*)b2[h])[d];
    }
    float x = fabsf(v1 - v2);
    #pragma unroll
    for (int off = 16; off; off >>= 1) x += __shfl_down_sync(0xffffffffu, x, off);
    __shared__ float ws[8];
    if ((tid & 31) == 0) ws[tid >> 5] = x;
    __syncthreads();
    if (d == 0) g_Dm[i] = ws[4 * h] + ws[4 * h + 1] + ws[4 * h + 2] + ws[4 * h + 3] + GAMMA;
}

// ---------------------------------------------------------------------------
// int8 SAD distances + per-chunk top-8 selection.
// Grid (128 tiles, 20 chunks, 2 sides), 512 threads, 2 CTAs/SM.
// NEW split: thread = ALL 8 anchors x 2 rows {2*tid, 2*tid+1}.
//   -> 1 LDG.64 per dim-group (halved), chunk read ONCE per CTA (was twice),
//      anchors via 2 broadcast LDS.128 per j ([j][t] layout). Same SAD count.
// ---------------------------------------------------------------------------
__global__ void __launch_bounds__(512, 2) k_dist() {
    int tile  = blockIdx.x;
    int chunk = blockIdx.y;
    int side  = blockIdx.z;
    int tid = threadIdx.x;

    __shared__ __align__(16) uint sh_aq[D / 4][TA];  // [j][t]: 1 KB
    __shared__ __align__(16) int sh_dist[TA][CROWS]; // 32 KB packed dists
    __shared__ int sh_cand[TA][2][KSEL];             // stage-1 candidates

    if (tid < (D / 4) * TA)
        sh_aq[tid >> 3][tid & 7] = g_anchq[side][tile * TA + (tid & 7)][tid >> 3];
    __syncthreads();

    uint acc[8][2];
    #pragma unroll
    for (int t = 0; t < 8; t++) { acc[t][0] = 0; acc[t][1] = 0; }

    const int p2 = 2 * tid;       // this thread's rows: p2, p2+1 (no duplication)
    const uint* __restrict__ qp = &g_qT[side][0][0] + chunk * CROWS + p2;

    #pragma unroll
    for (int j = 0; j < D / 4; j++) {
        uint2 b = *(const uint2*)(qp + (size_t)j * NPAD);   // rows p2, p2+1
        uint4 aL = *(const uint4*)&sh_aq[j][0];             // anchors 0-3 (bcast)
        uint4 aH = *(const uint4*)&sh_aq[j][4];             // anchors 4-7 (bcast)
        sad4(acc[0][0], aL.x, b.x); sad4(acc[0][1], aL.x, b.y);
        sad4(acc[1][0], aL.y, b.x); sad4(acc[1][1], aL.y, b.y);
        sad4(acc[2][0], aL.z, b.x); sad4(acc[2][1], aL.z, b.y);
        sad4(acc[3][0], aL.w, b.x); sad4(acc[3][1], aL.w, b.y);
        sad4(acc[4][0], aH.x, b.x); sad4(acc[4][1], aH.x, b.y);
        sad4(acc[5][0], aH.y, b.x); sad4(acc[5][1], aH.y, b.y);
        sad4(acc[6][0], aH.z, b.x); sad4(acc[6][1], aH.z, b.y);
        sad4(acc[7][0], aH.w, b.x); sad4(acc[7][1], aH.w, b.y);
    }

    // Store packed (sad<<10 | idx) as int2; invalid rows -> INT_MAX.
    const int nb = chunk * CROWS;
    const bool ok0 = (nb + p2) < NROWS, ok1 = (nb + p2 + 1) < NROWS;
    #pragma unroll
    for (int t = 0; t < 8; t++) {
        int2 v;
        v.x = ok0 ? (int)((acc[t][0] << 10) | (uint)p2)       : 0x7fffffff;
        v.y = ok1 ? (int)((acc[t][1] << 10) | (uint)(p2 + 1)) : 0x7fffffff;
        *(int2*)&sh_dist[t][p2] = v;
    }
    __syncthreads();

    int w = tid >> 5, lane = tid & 31;

    // Stage 1: warp w -> anchor (w&7), row-half (w>>3). Top-8 of 512 values.
    {
        int t = w & 7, hh = w >> 3;
        int* rowp = &sh_dist[t][hh * 512];
        #pragma unroll 1
        for (int it = 0; it < KSEL; it++) {
            int m = 0x7fffffff;
            #pragma unroll
            for (int k = 0; k < 4; k++) {
                int4 v = *(const int4*)&rowp[4 * lane + 128 * k];
                m = min(m, min(min(v.x, v.y), min(v.z, v.w)));
            }
            m = (int)__reduce_min_sync(0xffffffffu, (uint)m);
            if (lane == 0) sh_cand[t][hh][it] = m;
            int idx = m & 1023;
            int loc = idx - hh * 512;
            if (((loc >> 2) & 31) == lane) rowp[loc] = 0x7fffffff;
            __syncwarp();
        }
    }
    __syncthreads();

    // Stage 2: warps 0-7 merge the 16 candidates of anchor w -> final top-8.
    if (w < TA) {
        uint v = (lane < 2 * KSEL) ? (uint)sh_cand[w][lane >> 3][lane & 7]
                                   : 0xffffffffu;
        int aglob = tile * TA + w;
        #pragma unroll 1
        for (int it = 0; it < KSEL; it++) {
            uint m = __reduce_min_sync(0xffffffffu, v);
            if (lane == 0)
                g_candi[side][aglob][chunk * KSEL + it] = nb + (int)(m & 1023u);
            if (v == m) v = 0xffffffffu;   // packed values unique (idx bits)
        }
    }
}

// ---------------------------------------------------------------------------
// Exact fp32 repair + fused deterministic final reduction (last-block).
// ---------------------------------------------------------------------------
#define NCAND (NCHUNK * KSEL)   // 160
__global__ void __launch_bounds__(256) k_exact(const float* __restrict__ out1,
                                               const float* __restrict__ out2,
                                               float* __restrict__ out) {
    int a = blockIdx.x;               // 0..2047
    int side = a >> 10, ai = a & (NA - 1);
    int tid = threadIdx.x, lane = tid & 31;
    __shared__ __align__(16) float4 sh_a4[D / 4];
    __shared__ float sh_dv[NCAND];
    __shared__ float s[256];
    __shared__ bool amLast;

    if (tid < D / 4) sh_a4[tid] = ((const float4*)g_anch[side][ai])[tid];
    __syncthreads();

    if (tid < NCAND) {
        int ix = g_candi[side][ai][tid];
        const float* db = side ? out1 : out2;
        const float4* rp = (const float4*)(db + (size_t)ix * D);
        float s0 = 0.f, s1 = 0.f, s2 = 0.f, s3 = 0.f;
        #pragma unroll 8
        for (int j = 0; j < D / 4; j++) {
            float4 bv = rp[j];
            float4 av = sh_a4[j];
            s0 += fabsf(av.x - bv.x);
            s1 += fabsf(av.y - bv.y);
            s2 += fabsf(av.z - bv.z);
            s3 += fabsf(av.w - bv.w);
        }
        sh_dv[tid] = (s0 + s1) + (s2 + s3);
    }
    __syncthreads();

    if (tid < 32) {
        // lane holds 5 values (stride 32); nonneg floats order as uint bits.
        float v[5];
        #pragma unroll
        for (int k = 0; k < 5; k++) v[k] = sh_dv[lane + 32 * k];
        const float INF = __int_as_float(0x7f800000);
        float Dm = g_Dm[ai];
        float loss = 0.0f;
        #pragma unroll 1
        for (int it = 0; it < KTOP; it++) {
            uint mb = 0xffffffffu;
            #pragma unroll
            for (int k = 0; k < 5; k++) mb = min(mb, __float_as_uint(v[k]));
            mb = __reduce_min_sync(0xffffffffu, mb);
            float m = __uint_as_float(mb);
            loss += fmaxf(0.0f, Dm - m);
            bool have = (v[0] == m) | (v[1] == m) | (v[2] == m) |
                        (v[3] == m) | (v[4] == m);
            uint msk = __ballot_sync(0xffffffffu, have);
            if (lane == (int)(__ffs(msk) - 1)) {
                if      (v[0] == m) v[0] = INF;
                else if (v[1] == m) v[1] = INF;
                else if (v[2] == m) v[2] = INF;
                else if (v[3] == m) v[3] = INF;
                else                v[4] = INF;
            }
        }
        if (lane == 0) g_partial[a] = loss;
    }

    // Last-block deterministic final reduction.
    __syncthreads();
    __threadfence();                               // release g_partial[a]
    if (tid == 0) amLast = (atomicAdd(&g_done, 1u) == 2u * NA - 1u);
    __syncthreads();
    if (amLast) {
        __threadfence();                           // acquire all g_partial
        float v = 0.0f;
        #pragma unroll
        for (int k = 0; k < 8; k++) v += g_partial[tid + 256 * k];  // fixed order
        s[tid] = v;
        __syncthreads();
        for (int st = 128; st; st >>= 1) {
            if (tid < st) s[tid] += s[tid + st];
            __syncthreads();
        }
        if (tid == 0) out[0] = s[0] / (float)(NA * KTOP);
    }
}

// ---------------------------------------------------------------------------
extern "C" void kernel_launch(void* const* d_in, const int* in_sizes, int n_in,
                              void* d_out, int out_size) {
    const float* out1 = (const float*)d_in[0];
    const float* out2 = (const float*)d_in[1];
    const int*   an1  = (const int*)d_in[2];
    const int*   an2  = (const int*)d_in[3];
    float* out = (float*)d_out;

    k_prep<<<2 * QBLK + NA / 2, 256>>>(out1, out2, an1, an2);
    k_dist<<<dim3(NA / TA, NCHUNK, 2), 512>>>();
    k_exact<<<2 * NA, 256>>>(out1, out2, out);
}

// round 17
// speedup vs baseline: 1.2603x; 1.1163x over previous
#include <cuda_runtime.h>
#include <cstdint>

#define D       128
#define NROWS   20000
#define NPAD    20480
#define NA      1024
#define TA      8         // anchors per CTA
#define CROWS   1024
#define NCHUNK  20
#define KSEL    8
#define KTOP    10
#define GAMMA   1.0f
#define SCALE   25.4f     // int8 quant scale, selection-only
#define QBLK    625       // quant blocks per side (625*32 = 20000 exactly)

typedef unsigned int uint;

// Static device scratch (allocation-free rule: __device__ globals only)
__device__ __align__(16) uint g_qT[2][D / 4][NPAD];     // transposed packed DB
__device__ __align__(16) uint g_anchq[2][NA][D / 4];    // packed quantized anchors
__device__ __align__(16) float g_anch[2][NA][D];        // fp32 anchors
__device__ float g_Dm[NA];                              // positive dist + gamma
__device__ int   g_candi[2][NA][NCHUNK * KSEL];         // candidate row indices
__device__ float g_partial[2 * NA];                     // per-anchor loss
__device__ uint  g_done;                                // last-block counter

// Fused SAD-accumulate: acc += sum_bytes(|s8(a) - s8(b)|)  (single SASS op)
__device__ __forceinline__ void sad4(uint& acc, uint a, uint b) {
    asm("vabsdiff4.u32.s32.s32.add %0, %1, %2, %0;" : "+r"(acc) : "r"(a), "r"(b));
}

// ---------------------------------------------------------------------------
// Prep (measured 8us): quantize+transpose DBs via coalesced smem transpose
// (32 rows/block), then gather anchors (2/block). Resets g_done.
// ---------------------------------------------------------------------------
__global__ void k_prep(const float* __restrict__ out1,
                       const float* __restrict__ out2,
                       const int* __restrict__ an1,
                       const int* __restrict__ an2) {
    int b = blockIdx.x;
    int tid = threadIdx.x;
    if (b == 0 && tid == 0) g_done = 0;

    if (b < 2 * QBLK) {
        int side = (b >= QBLK);
        int r0 = (side ? b - QBLK : b) * 32;
        const float* src = side ? out1 : out2;
        __shared__ unsigned char qb[32][132];   // 132-byte pad: conflict-free
        #pragma unroll
        for (int k = 0; k < 16; k++) {
            int idx = tid + k * 256;            // 0..4095
            int row = idx >> 7, dim = idx & 127;
            float v = src[(size_t)(r0 + row) * D + dim];
            int q = __float2int_rn(fminf(fmaxf(v * SCALE, -127.f), 127.f));
            qb[row][dim] = (unsigned char)q;
        }
        __syncthreads();
        int lane = tid & 31, wj = tid >> 5;
        #pragma unroll
        for (int k = 0; k < 4; k++) {
            int j = wj + 8 * k;
            uint p = *(const uint*)&qb[lane][4 * j];   // dims 4j..4j+3 packed
            g_qT[side][j][r0 + lane] = p;              // coalesced over lanes
        }
        return;
    }
    // gather: 2 anchors per block, 128 threads each
    int i = (b - 2 * QBLK) * 2 + (tid >> 7);
    int d = tid & 127;
    float v1 = out1[(size_t)an1[i] * D + d];
    float v2 = out2[(size_t)an2[i] * D + d];
    g_anch[0][i][d] = v1;
    g_anch[1][i][d] = v2;
    int q1 = __float2int_rn(fminf(fmaxf(v1 * SCALE, -127.f), 127.f)) & 255;
    int q2 = __float2int_rn(fminf(fmaxf(v2 * SCALE, -127.f), 127.f)) & 255;
    __shared__ unsigned char b1[2][D], b2[2][D];
    int h = tid >> 7;
    b1[h][d] = (unsigned char)q1;
    b2[h][d] = (unsigned char)q2;
    __syncthreads();
    if (d < D / 4) {
        g_anchq[0][i][d] = ((const uint*)b1[h])[d];
        g_anchq[1][i][d] = ((const uint*)b2[h])[d];
    }
    float x = fabsf(v1 - v2);
    #pragma unroll
    for (int off = 16; off; off >>= 1) x += __shfl_down_sync(0xffffffffu, x, off);
    __shared__ float ws[8];
    if ((tid & 31) == 0) ws[tid >> 5] = x;
    __syncthreads();
    if (d == 0) g_Dm[i] = ws[4 * h] + ws[4 * h + 1] + ws[4 * h + 2] + ws[4 * h + 3] + GAMMA;
}

// ---------------------------------------------------------------------------
// int8 SAD distances + per-chunk top-8 selection.
// Grid (128 tiles, 20 chunks, 2 sides), 256 threads, 3 CTAs/SM (85-reg budget:
// no spill cliff). Thread = ALL 8 anchors x 4 rows {4t..4t+3}:
// per dim-group 1 LDG.128 + 2 bcast LDS.128 + 32 SAD (overhead/SAD halved).
// ---------------------------------------------------------------------------
__global__ void __launch_bounds__(256, 3) k_dist() {
    int tile  = blockIdx.x;
    int chunk = blockIdx.y;
    int side  = blockIdx.z;
    int tid = threadIdx.x;

    __shared__ __align__(16) uint sh_aq[D / 4][TA];  // [j][t]: 1 KB
    __shared__ __align__(16) int sh_dist[TA][CROWS]; // 32 KB packed dists

    // 256 threads load all 256 anchor words.
    sh_aq[tid >> 3][tid & 7] = g_anchq[side][tile * TA + (tid & 7)][tid >> 3];
    __syncthreads();

    uint acc[8][4];
    #pragma unroll
    for (int t = 0; t < 8; t++)
        #pragma unroll
        for (int r = 0; r < 4; r++) acc[t][r] = 0;

    const int p4 = 4 * tid;       // rows p4..p4+3 (256 threads x 4 = 1024 rows)
    const uint* __restrict__ qp = &g_qT[side][0][0] + chunk * CROWS + p4;

    #pragma unroll
    for (int j = 0; j < D / 4; j++) {
        uint4 b  = *(const uint4*)(qp + (size_t)j * NPAD);  // rows p4..p4+3
        uint4 aL = *(const uint4*)&sh_aq[j][0];             // anchors 0-3 (bcast)
        uint4 aH = *(const uint4*)&sh_aq[j][4];             // anchors 4-7 (bcast)
        sad4(acc[0][0], aL.x, b.x); sad4(acc[0][1], aL.x, b.y);
        sad4(acc[0][2], aL.x, b.z); sad4(acc[0][3], aL.x, b.w);
        sad4(acc[1][0], aL.y, b.x); sad4(acc[1][1], aL.y, b.y);
        sad4(acc[1][2], aL.y, b.z); sad4(acc[1][3], aL.y, b.w);
        sad4(acc[2][0], aL.z, b.x); sad4(acc[2][1], aL.z, b.y);
        sad4(acc[2][2], aL.z, b.z); sad4(acc[2][3], aL.z, b.w);
        sad4(acc[3][0], aL.w, b.x); sad4(acc[3][1], aL.w, b.y);
        sad4(acc[3][2], aL.w, b.z); sad4(acc[3][3], aL.w, b.w);
        sad4(acc[4][0], aH.x, b.x); sad4(acc[4][1], aH.x, b.y);
        sad4(acc[4][2], aH.x, b.z); sad4(acc[4][3], aH.x, b.w);
        sad4(acc[5][0], aH.y, b.x); sad4(acc[5][1], aH.y, b.y);
        sad4(acc[5][2], aH.y, b.z); sad4(acc[5][3], aH.y, b.w);
        sad4(acc[6][0], aH.z, b.x); sad4(acc[6][1], aH.z, b.y);
        sad4(acc[6][2], aH.z, b.z); sad4(acc[6][3], aH.z, b.w);
        sad4(acc[7][0], aH.w, b.x); sad4(acc[7][1], aH.w, b.y);
        sad4(acc[7][2], aH.w, b.z); sad4(acc[7][3], aH.w, b.w);
    }

    // Store packed (sad<<10 | idx) as int4; invalid rows -> INT_MAX.
    const int nb = chunk * CROWS;
    #pragma unroll
    for (int t = 0; t < 8; t++) {
        int4 v;
        v.x = (nb + p4     < NROWS) ? (int)((acc[t][0] << 10) | (uint)(p4))     : 0x7fffffff;
        v.y = (nb + p4 + 1 < NROWS) ? (int)((acc[t][1] << 10) | (uint)(p4 + 1)) : 0x7fffffff;
        v.z = (nb + p4 + 2 < NROWS) ? (int)((acc[t][2] << 10) | (uint)(p4 + 2)) : 0x7fffffff;
        v.w = (nb + p4 + 3 < NROWS) ? (int)((acc[t][3] << 10) | (uint)(p4 + 3)) : 0x7fffffff;
        *(int4*)&sh_dist[t][p4] = v;
    }
    __syncthreads();

    // Selection: warp w owns anchor w (8 warps, all busy), top-8 of 1024.
    int w = tid >> 5, lane = tid & 31;
    int* row = sh_dist[w];
    int aglob = tile * TA + w;
    #pragma unroll 1
    for (int it = 0; it < KSEL; it++) {
        int m = 0x7fffffff;
        #pragma unroll
        for (int k = 0; k < 8; k++) {
            int4 v = *(const int4*)&row[4 * lane + 128 * k];
            m = min(m, min(min(v.x, v.y), min(v.z, v.w)));
        }
        m = (int)__reduce_min_sync(0xffffffffu, (uint)m);
        int idx = m & 1023;
        if (lane == 0)
            g_candi[side][aglob][chunk * KSEL + it] = nb + idx;
        if (((idx >> 2) & 31) == lane) row[idx] = 0x7fffffff;
        __syncwarp();
    }
}

// ---------------------------------------------------------------------------
// Exact fp32 repair + fused deterministic final reduction (last-block).
// ---------------------------------------------------------------------------
#define NCAND (NCHUNK * KSEL)   // 160
__global__ void __launch_bounds__(256) k_exact(const float* __restrict__ out1,
                                               const float* __restrict__ out2,
                                               float* __restrict__ out) {
    int a = blockIdx.x;               // 0..2047
    int side = a >> 10, ai = a & (NA - 1);
    int tid = threadIdx.x, lane = tid & 31;
    __shared__ __align__(16) float4 sh_a4[D / 4];
    __shared__ float sh_dv[NCAND];
    __shared__ float s[256];
    __shared__ bool amLast;

    if (tid < D / 4) sh_a4[tid] = ((const float4*)g_anch[side][ai])[tid];
    __syncthreads();

    if (tid < NCAND) {
        int ix = g_candi[side][ai][tid];
        const float* db = side ? out1 : out2;
        const float4* rp = (const float4*)(db + (size_t)ix * D);
        float s0 = 0.f, s1 = 0.f, s2 = 0.f, s3 = 0.f;
        #pragma unroll 8
        for (int j = 0; j < D / 4; j++) {
            float4 bv = rp[j];
            float4 av = sh_a4[j];
            s0 += fabsf(av.x - bv.x);
            s1 += fabsf(av.y - bv.y);
            s2 += fabsf(av.z - bv.z);
            s3 += fabsf(av.w - bv.w);
        }
        sh_dv[tid] = (s0 + s1) + (s2 + s3);
    }
    __syncthreads();

    if (tid < 32) {
        // lane holds 5 values (stride 32); nonneg floats order as uint bits.
        float v[5];
        #pragma unroll
        for (int k = 0; k < 5; k++) v[k] = sh_dv[lane + 32 * k];
        const float INF = __int_as_float(0x7f800000);
        float Dm = g_Dm[ai];
        float loss = 0.0f;
        #pragma unroll 1
        for (int it = 0; it < KTOP; it++) {
            uint mb = 0xffffffffu;
            #pragma unroll
            for (int k = 0; k < 5; k++) mb = min(mb, __float_as_uint(v[k]));
            mb = __reduce_min_sync(0xffffffffu, mb);
            float m = __uint_as_float(mb);
            loss += fmaxf(0.0f, Dm - m);
            bool have = (v[0] == m) | (v[1] == m) | (v[2] == m) |
                        (v[3] == m) | (v[4] == m);
            uint msk = __ballot_sync(0xffffffffu, have);
            if (lane == (int)(__ffs(msk) - 1)) {
                if      (v[0] == m) v[0] = INF;
                else if (v[1] == m) v[1] = INF;
                else if (v[2] == m) v[2] = INF;
                else if (v[3] == m) v[3] = INF;
                else                v[4] = INF;
            }
        }
        if (lane == 0) g_partial[a] = loss;
    }

    // Last-block deterministic final reduction.
    __syncthreads();
    __threadfence();                               // release g_partial[a]
    if (tid == 0) amLast = (atomicAdd(&g_done, 1u) == 2u * NA - 1u);
    __syncthreads();
    if (amLast) {
        __threadfence();                           // acquire all g_partial
        float v = 0.0f;
        #pragma unroll
        for (int k = 0; k < 8; k++) v += g_partial[tid + 256 * k];  // fixed order
        s[tid] = v;
        __syncthreads();
        for (int st = 128; st; st >>= 1) {
            if (tid < st) s[tid] += s[tid + st];
            __syncthreads();
        }
        if (tid == 0) out[0] = s[0] / (float)(NA * KTOP);
    }
}

// ---------------------------------------------------------------------------
extern "C" void kernel_launch(void* const* d_in, const int* in_sizes, int n_in,
                              void* d_out, int out_size) {
    const float* out1 = (const float*)d_in[0];
    const float* out2 = (const float*)d_in[1];
    const int*   an1  = (const int*)d_in[2];
    const int*   an2  = (const int*)d_in[3];
    float* out = (float*)d_out;

    k_prep<<<2 * QBLK + NA / 2, 256>>>(out1, out2, an1, an2);
    k_dist<<<dim3(NA / TA, NCHUNK, 2), 256>>>();
    k_exact<<<2 * NA, 256>>>(out1, out2, out);
}